// round 2
// baseline (speedup 1.0000x reference)
#include <cuda_runtime.h>
#include <math.h>

// ---------------- problem constants ----------------
#define BATCH   8
#define CIN     512
#define COUT    512
#define WDIM    512
#define INS     64          // input spatial
#define Y1S     66          // conv output spatial (64 + 2*2 - 3 + 1)
#define PLANE   (Y1S*Y1S)   // 4356
#define UPS     138         // after up-FIR
#define OUTS    64

// ---------------- device scratch ----------------
__device__ float g_styles[BATCH*CIN];          // normalized styles
__device__ float g_filter[12];                 // shared up/down FIR taps
__device__ float g_wn[COUT*CIN*9];             // per-oc normalized weights
__device__ float g_W2[COUT*CIN];               // sum_k wn^2
__device__ float g_d[BATCH*COUT];              // demod coefficients
__device__ float g_y1[BATCH*COUT*PLANE];       // conv output (+bias, demod)

// ---------------- helpers ----------------
__device__ double bessel_i0(double x) {
    double t = x * x * 0.25;
    double term = 1.0, s = 1.0;
    for (int k = 1; k < 64; k++) {
        term *= t / ((double)k * (double)k);
        s += term;
        if (term < 1e-18 * s) break;
    }
    return s;
}

// ============ K0: filter design + styles GEMM + global style norm ============
__global__ void k0_styles_filter(const float* __restrict__ w,
                                 const float* __restrict__ A,
                                 const float* __restrict__ bias) {
    int i = threadIdx.x; // 0..511 (one per CIN channel)

    if (i == 0) {
        // kaiser beta for (numtaps=12, width=32, fs=128)
        const double PI = 3.14159265358979323846;
        double a = 2.285 * 11.0 * PI * (32.0 / 64.0) + 7.95;
        double beta;
        if (a > 50.0)      beta = 0.1102 * (a - 8.7);
        else if (a > 21.0) beta = 0.5842 * pow(a - 21.0, 0.4) + 0.07886 * (a - 21.0);
        else               beta = 0.0;
        double i0b = bessel_i0(beta);
        double h[12], sum = 0.0;
        const double c = 0.5; // cutoff/(fs/2)
        for (int n = 0; n < 12; n++) {
            double m = (double)n - 5.5;
            double sx = c * m;
            double sinc = (sx == 0.0) ? 1.0 : sin(PI * sx) / (PI * sx);
            double ratio = m / 5.5;
            double karg = beta * sqrt(fmax(0.0, 1.0 - ratio * ratio));
            h[n] = c * sinc * bessel_i0(karg) / i0b;
            sum += h[n];
        }
        for (int n = 0; n < 12; n++) g_filter[n] = (float)(h[n] / sum);
    }

    // styles[b][i] = sum_k w[b][k]*A[i][k] * (1/sqrt(512)) + bias[i]
    float acc[BATCH];
#pragma unroll
    for (int b = 0; b < BATCH; b++) acc[b] = 0.f;
    const float* Ai = A + (size_t)i * WDIM;
    for (int k = 0; k < WDIM; k++) {
        float av = Ai[k];
#pragma unroll
        for (int b = 0; b < BATCH; b++) acc[b] += w[b * WDIM + k] * av;
    }
    const float cc = 0.04419417382415922f; // 1/sqrt(512)
    float bi = bias[i];
    float p = 0.f;
#pragma unroll
    for (int b = 0; b < BATCH; b++) {
        acc[b] = acc[b] * cc + bi;
        p += acc[b] * acc[b];
    }
    __shared__ float red[512];
    red[i] = p;
    __syncthreads();
    for (int s = 256; s > 0; s >>= 1) {
        if (i < s) red[i] += red[i + s];
        __syncthreads();
    }
    float scale = rsqrtf(red[0] * (1.0f / (BATCH * CIN)));
#pragma unroll
    for (int b = 0; b < BATCH; b++) g_styles[b * CIN + i] = acc[b] * scale;
}

// ============ K1: weight normalization + W2 ============
__global__ void k1_wnorm(const float* __restrict__ cw) {
    int o = blockIdx.x, tid = threadIdx.x;
    const float* wo = cw + (size_t)o * (CIN * 9);
    __shared__ float red[256];
    float ss = 0.f;
    for (int t = tid; t < CIN * 9; t += 256) { float v = wo[t]; ss += v * v; }
    red[tid] = ss;
    __syncthreads();
    for (int s = 128; s > 0; s >>= 1) {
        if (tid < s) red[tid] += red[tid + s];
        __syncthreads();
    }
    float r = rsqrtf(red[0] * (1.0f / (CIN * 9)));
    for (int t = tid; t < CIN * 9; t += 256) g_wn[(size_t)o * (CIN * 9) + t] = wo[t] * r;
    float r2 = r * r;
    for (int i = tid; i < CIN; i += 256) {
        float s9 = 0.f;
#pragma unroll
        for (int k = 0; k < 9; k++) { float v = wo[i * 9 + k]; s9 += v * v; }
        g_W2[o * CIN + i] = s9 * r2;
    }
}

// ============ K2: demodulation coefficients ============
__global__ void k2_demod() {
    int b = blockIdx.x, o = threadIdx.x;
    __shared__ float s2[CIN];
    float sv = g_styles[b * CIN + o];
    s2[o] = sv * sv;
    __syncthreads();
    const float* w2 = g_W2 + (size_t)o * CIN;
    float acc = 0.f;
    for (int i = 0; i < CIN; i++) acc += s2[i] * w2[i];
    g_d[b * COUT + o] = rsqrtf(acc + 1e-8f);
}

// ============ K3: modulated conv (direct, fp32) ============
// grid (9 spatial tiles of 22x22, 32 oc-groups of 16, 8 batch), 128 threads.
// thread (i,j) in 11x11 computes a 2x2 pixel micro-tile for 16 out channels.
__global__ __launch_bounds__(128)
void k3_conv(const float* __restrict__ x, const float* __restrict__ cbias) {
    int tileid = blockIdx.x;      // 0..8
    int og = blockIdx.y;          // 0..31
    int b  = blockIdx.z;          // 0..7
    int tr = tileid / 3, tc = tileid % 3;
    int o0 = og * 16;
    int tid = threadIdx.x;

    __shared__ float xs[8][24][25];   // input tile (with 2-halo each side), padded stride
    __shared__ float ws[16][8][9];    // weights [oc][ic][k]

    float acc[64];
#pragma unroll
    for (int t = 0; t < 64; t++) acc[t] = 0.f;

    int r0 = tr * 22 - 2;
    int q0 = tc * 22 - 2;

    int ii = tid / 11, jj = tid % 11;     // compute mapping (valid if tid<121)
    int pr = 2 * ii, pc = 2 * jj;

    for (int c0 = 0; c0 < CIN; c0 += 8) {
        // load x tile (style-scaled, zero-padded)
        for (int t = tid; t < 8 * 24 * 24; t += 128) {
            int c = t / 576, rem = t % 576, r = rem / 24, q = rem % 24;
            int gr = r0 + r, gq = q0 + q;
            float v = 0.f;
            if (gr >= 0 && gr < INS && gq >= 0 && gq < INS)
                v = x[(((size_t)b * CIN + c0 + c) * INS + gr) * INS + gq] *
                    g_styles[b * CIN + c0 + c];
            xs[c][r][q] = v;
        }
        // load weights
        for (int t = tid; t < 1152; t += 128) {
            int oc = t / 72, rem = t % 72, c = rem / 9, k = rem % 9;
            ws[oc][c][k] = g_wn[((size_t)(o0 + oc) * CIN + c0 + c) * 9 + k];
        }
        __syncthreads();

        if (tid < 121) {
#pragma unroll 2
            for (int c = 0; c < 8; c++) {
                float xv[16];
#pragma unroll
                for (int r = 0; r < 4; r++)
#pragma unroll
                    for (int q = 0; q < 4; q++)
                        xv[r * 4 + q] = xs[c][pr + r][pc + q];
#pragma unroll
                for (int oc = 0; oc < 16; oc++) {
                    float w0 = ws[oc][c][0], w1 = ws[oc][c][1], w2 = ws[oc][c][2];
                    float w3 = ws[oc][c][3], w4 = ws[oc][c][4], w5 = ws[oc][c][5];
                    float w6 = ws[oc][c][6], w7 = ws[oc][c][7], w8 = ws[oc][c][8];
#pragma unroll
                    for (int dr = 0; dr < 2; dr++)
#pragma unroll
                        for (int dq = 0; dq < 2; dq++) {
                            float a = acc[oc * 4 + dr * 2 + dq];
                            a += w0 * xv[(dr + 0) * 4 + dq + 0];
                            a += w1 * xv[(dr + 0) * 4 + dq + 1];
                            a += w2 * xv[(dr + 0) * 4 + dq + 2];
                            a += w3 * xv[(dr + 1) * 4 + dq + 0];
                            a += w4 * xv[(dr + 1) * 4 + dq + 1];
                            a += w5 * xv[(dr + 1) * 4 + dq + 2];
                            a += w6 * xv[(dr + 2) * 4 + dq + 0];
                            a += w7 * xv[(dr + 2) * 4 + dq + 1];
                            a += w8 * xv[(dr + 2) * 4 + dq + 2];
                            acc[oc * 4 + dr * 2 + dq] = a;
                        }
                }
            }
        }
        __syncthreads();
    }

    if (tid < 121) {
#pragma unroll
        for (int oc = 0; oc < 16; oc++) {
            int o = o0 + oc;
            float dm = g_d[b * COUT + o];
            float bi = cbias[o];
#pragma unroll
            for (int dr = 0; dr < 2; dr++)
#pragma unroll
                for (int dq = 0; dq < 2; dq++) {
                    int P = tr * 22 + pr + dr;
                    int Q = tc * 22 + pc + dq;
                    g_y1[(((size_t)b * COUT + o) * Y1S + P) * Y1S + Q] =
                        acc[oc * 4 + dr * 2 + dq] * dm + bi;
                }
        }
    }
}

// ============ K4: fused upFIR -> lrelu/clamp -> downFIR (one block per plane) =
// smem: sy1 66*66 (4356) | vt 138*66 (9108, reused as dvt 64*138) | act 138*139
#define SM_SY1 0
#define SM_VT  4356
#define SM_ACT (4356 + 9108)
#define SM_FLOATS (4356 + 9108 + 138*139)

// polyphase up tap: src indexed [n>>1], valid if 0 <= n < 132
#define UTAPC(T, FI, LOADEXPR) { int n = rr + (T) - 9; if (n >= 0 && n < 132) { int jph = n >> 1; acc += (LOADEXPR) * fl[FI]; } }

__global__ __launch_bounds__(256)
void k4_fir(float* __restrict__ out) {
    int plane = blockIdx.x;              // b*512 + ch
    int tid = threadIdx.x;
    extern __shared__ float sm[];
    float* sy1 = sm + SM_SY1;
    float* vt  = sm + SM_VT;
    float* act = sm + SM_ACT;

    float fl[12];
#pragma unroll
    for (int k = 0; k < 12; k++) fl[k] = g_filter[k];

    // phase 1: load conv output plane
    const float* src = g_y1 + (size_t)plane * PLANE;
    for (int t = tid; t < PLANE; t += 256) sy1[t] = src[t];
    __syncthreads();

    // phase 2: vertical up-FIR (polyphase), gain 4 applied here. vt[138][66]
    for (int e = tid; e < UPS * Y1S; e += 256) {
        int rr = e / Y1S, i = e - rr * Y1S;
        float acc = 0.f;
        if ((rr & 1) == 0) { // even rows use odd taps
            UTAPC(1,  10, sy1[jph * Y1S + i]);
            UTAPC(3,   8, sy1[jph * Y1S + i]);
            UTAPC(5,   6, sy1[jph * Y1S + i]);
            UTAPC(7,   4, sy1[jph * Y1S + i]);
            UTAPC(9,   2, sy1[jph * Y1S + i]);
            UTAPC(11,  0, sy1[jph * Y1S + i]);
        } else {             // odd rows use even taps
            UTAPC(0,  11, sy1[jph * Y1S + i]);
            UTAPC(2,   9, sy1[jph * Y1S + i]);
            UTAPC(4,   7, sy1[jph * Y1S + i]);
            UTAPC(6,   5, sy1[jph * Y1S + i]);
            UTAPC(8,   3, sy1[jph * Y1S + i]);
            UTAPC(10,  1, sy1[jph * Y1S + i]);
        }
        vt[e] = 4.f * acc;
    }
    __syncthreads();

    // phase 3: horizontal up-FIR + lrelu*sqrt2 + clamp. act[138][139 stride]
    for (int e = tid; e < UPS * UPS; e += 256) {
        int r = e / UPS, rr = e - r * UPS; // rr = output column here
        const float* vr = vt + r * Y1S;
        float acc = 0.f;
        if ((rr & 1) == 0) {
            UTAPC(1,  10, vr[jph]);
            UTAPC(3,   8, vr[jph]);
            UTAPC(5,   6, vr[jph]);
            UTAPC(7,   4, vr[jph]);
            UTAPC(9,   2, vr[jph]);
            UTAPC(11,  0, vr[jph]);
        } else {
            UTAPC(0,  11, vr[jph]);
            UTAPC(2,   9, vr[jph]);
            UTAPC(4,   7, vr[jph]);
            UTAPC(6,   5, vr[jph]);
            UTAPC(8,   3, vr[jph]);
            UTAPC(10,  1, vr[jph]);
        }
        float a = (acc >= 0.f ? acc : 0.2f * acc) * 1.4142135623730951f;
        a = fminf(fmaxf(a, -256.f), 256.f);
        act[r * 139 + rr] = a;
    }
    __syncthreads();

    // phase 4: vertical down-FIR with stride-2 rows. dvt (in vt) [64][138]
    for (int e = tid; e < OUTS * UPS; e += 256) {
        int rr = e / UPS, j = e - rr * UPS;
        const float* ap = act + (2 * rr) * 139 + j;
        float acc = 0.f;
#pragma unroll
        for (int t = 0; t < 12; t++) acc += fl[11 - t] * ap[t * 139];
        vt[rr * UPS + j] = acc;
    }
    __syncthreads();

    // phase 5: horizontal down-FIR, stride 2, write output
    float* dst = out + (size_t)plane * (OUTS * OUTS);
    for (int e = tid; e < OUTS * OUTS; e += 256) {
        int rr = e / OUTS, cc = e - rr * OUTS;
        const float* dp = vt + rr * UPS + 2 * cc;
        float acc = 0.f;
#pragma unroll
        for (int t = 0; t < 12; t++) acc += fl[11 - t] * dp[t];
        dst[rr * OUTS + cc] = acc;
    }
}

// ============ launch ============
extern "C" void kernel_launch(void* const* d_in, const int* in_sizes, int n_in,
                              void* d_out, int out_size) {
    const float* x   = (const float*)d_in[0];
    const float* w   = (const float*)d_in[1];
    const float* A   = (const float*)d_in[2];
    const float* ab  = (const float*)d_in[3];
    const float* cw  = (const float*)d_in[4];
    const float* cb  = (const float*)d_in[5];
    float* out = (float*)d_out;

    cudaFuncSetAttribute(k4_fir, cudaFuncAttributeMaxDynamicSharedMemorySize,
                         SM_FLOATS * sizeof(float));

    k0_styles_filter<<<1, 512>>>(w, A, ab);
    k1_wnorm<<<COUT, 256>>>(cw);
    k2_demod<<<BATCH, COUT>>>();
    k3_conv<<<dim3(9, 32, BATCH), 128>>>(x, cb);
    k4_fir<<<BATCH * COUT, 256, SM_FLOATS * sizeof(float)>>>(out);
}

// round 5
// speedup vs baseline: 1.6310x; 1.6310x over previous
#include <cuda_runtime.h>
#include <cuda_fp16.h>
#include <cstdint>
#include <math.h>

#define BATCH 8
#define CIN   512
#define COUT  512
#define WDIM  512
#define INS   64
#define Y1S   66
#define PLANE 4356
#define UPS   138
#define OUTS  64
#define KTOT  4608
#define XPH   68
#define XPW   72
#define XPL   (XPH*XPW)   // 4896

__device__ float    g_styles[BATCH*CIN];
__device__ float    g_filter[12];
__device__ __half   g_wh[COUT*KTOT];
__device__ __half   g_wl[COUT*KTOT];
__device__ float    g_W2[COUT*CIN];
__device__ float    g_d[BATCH*COUT];
__device__ float    g_y1[BATCH*COUT*PLANE];
__device__ uint32_t g_xhl[BATCH*CIN*XPL];   // per pixel: (lo16<<16)|hi16

// ---------------- PTX helpers (sm_80-baseline only) ----------------
__device__ __forceinline__ uint32_t smem_u32(const void* p) {
    uint32_t a;
    asm("{ .reg .u64 t; cvta.to.shared.u64 t, %1; cvt.u32.u64 %0, t; }" : "=r"(a) : "l"(p));
    return a;
}
#define CP16(dst, src) \
    asm volatile("cp.async.cg.shared.global [%0], [%1], 16;" :: "r"(dst), "l"(src))
#define CPC() asm volatile("cp.async.commit_group;")
#define LDSM4(R, ad) \
    asm volatile("ldmatrix.sync.aligned.m8n8.x4.shared.b16 {%0,%1,%2,%3}, [%4];" \
        : "=r"((R)[0]), "=r"((R)[1]), "=r"((R)[2]), "=r"((R)[3]) : "r"(ad))
#define LDSM4T(R, ad) \
    asm volatile("ldmatrix.sync.aligned.m8n8.x4.trans.shared.b16 {%0,%1,%2,%3}, [%4];" \
        : "=r"((R)[0]), "=r"((R)[1]), "=r"((R)[2]), "=r"((R)[3]) : "r"(ad))
#define MMA(d, a, b0, b1) \
    asm volatile("mma.sync.aligned.m16n8k16.row.col.f32.f16.f16.f32 " \
        "{%0,%1,%2,%3}, {%4,%5,%6,%7}, {%8,%9}, {%0,%1,%2,%3};" \
        : "+f"((d)[0]), "+f"((d)[1]), "+f"((d)[2]), "+f"((d)[3]) \
        : "r"((a)[0]), "r"((a)[1]), "r"((a)[2]), "r"((a)[3]), "r"(b0), "r"(b1))

// atom(32px) -> plane pixel map; atoms 0..136 real. Pairs (j even, j+1) are
// always contiguous pixels and both-valid / both-invalid.
__device__ __forceinline__ bool atom_pix(int a, int j, int& P, int& Q) {
    if (a >= 137) return false;
    if (a < 132) {
        int blk = a / 33, ww = a - blk * 33;
        if (ww < 32) { P = blk*16 + (ww>>1); Q = ((ww&1)<<5) + j; return true; }
        P = blk*16 + (j>>1); Q = 64 + (j&1); return true;
    }
    if (a < 136) { int ww = a - 132; P = 64 + (ww>>1); Q = ((ww&1)<<5) + j; return true; }
    P = 64 + (j>>1); Q = 64 + (j&1); return (j < 4);
}
__device__ double bessel_i0(double x) {
    double t = x*x*0.25, term = 1.0, s = 1.0;
    for (int k = 1; k < 64; k++) { term *= t/((double)k*(double)k); s += term; if (term < 1e-18*s) break; }
    return s;
}
__device__ __forceinline__ void split2(float v, __half& h, __half& l) {
    h = __float2half_rn(v);
    l = __float2half_rn(v - __half2float(h));
}

// ============ K0: filter + styles + global style norm ============
__global__ void k0_styles(const float* __restrict__ w, const float* __restrict__ A,
                          const float* __restrict__ bias) {
    int i = threadIdx.x;
    if (i == 0) {
        const double PI = 3.14159265358979323846;
        double a = 2.285*11.0*PI*0.5 + 7.95;
        double beta = (a > 50.0) ? 0.1102*(a-8.7)
                     : (a > 21.0) ? 0.5842*pow(a-21.0,0.4)+0.07886*(a-21.0) : 0.0;
        double i0b = bessel_i0(beta), h[12], sum = 0.0;
        for (int n = 0; n < 12; n++) {
            double m = n - 5.5, sx = 0.5*m;
            double sinc = (sx==0.0) ? 1.0 : sin(PI*sx)/(PI*sx);
            double rt = m/5.5;
            h[n] = 0.5*sinc*bessel_i0(beta*sqrt(fmax(0.0,1.0-rt*rt)))/i0b;
            sum += h[n];
        }
        for (int n = 0; n < 12; n++) g_filter[n] = (float)(h[n]/sum);
    }
    float acc[BATCH];
#pragma unroll
    for (int b = 0; b < BATCH; b++) acc[b] = 0.f;
    const float* Ai = A + (size_t)i*WDIM;
    for (int k = 0; k < WDIM; k++) {
        float av = Ai[k];
#pragma unroll
        for (int b = 0; b < BATCH; b++) acc[b] += w[b*WDIM+k]*av;
    }
    float bi = bias[i], p = 0.f;
#pragma unroll
    for (int b = 0; b < BATCH; b++) { acc[b] = acc[b]*0.04419417382415922f + bi; p += acc[b]*acc[b]; }
    __shared__ float red[512];
    red[i] = p; __syncthreads();
    for (int s = 256; s > 0; s >>= 1) { if (i < s) red[i] += red[i+s]; __syncthreads(); }
    float sc = rsqrtf(red[0]*(1.0f/(BATCH*CIN)));
#pragma unroll
    for (int b = 0; b < BATCH; b++) g_styles[b*CIN+i] = acc[b]*sc;
}

// ============ K_pad: padded style-scaled packed fp16-split input ============
__global__ void k_pad(const float* __restrict__ x) {
    int idx = blockIdx.x*256 + threadIdx.x;
    if (idx >= BATCH*CIN*XPL) return;
    int col = idx % XPW, row = (idx/XPW) % XPH;
    int c = (idx/XPL) % CIN, b = idx/(XPL*CIN);
    int ri = row - 2, ci = col - 2;
    float v = 0.f;
    if (ri >= 0 && ri < INS && ci >= 0 && ci < INS)
        v = x[(((size_t)b*CIN+c)*INS+ri)*INS+ci] * g_styles[b*CIN+c];
    __half h, l; split2(v, h, l);
    g_xhl[idx] = ((uint32_t)__half_as_ushort(l) << 16) | (uint32_t)__half_as_ushort(h);
}

// ============ K1: weight norm + split + W2 ============
__global__ void k1_wnorm(const float* __restrict__ cw) {
    int o = blockIdx.x, tid = threadIdx.x;
    const float* wo = cw + (size_t)o*(CIN*9);
    __shared__ float red[256];
    float ss = 0.f;
    for (int t = tid; t < CIN*9; t += 256) { float v = wo[t]; ss += v*v; }
    red[tid] = ss; __syncthreads();
    for (int s = 128; s > 0; s >>= 1) { if (tid < s) red[tid] += red[tid+s]; __syncthreads(); }
    float r = rsqrtf(red[0]*(1.0f/(CIN*9)));
    for (int t = tid; t < CIN*9; t += 256) {
        int i = t/9, kk = t - i*9;
        __half h, l; split2(wo[t]*r, h, l);
        g_wh[(size_t)o*KTOT + kk*512 + i] = h;
        g_wl[(size_t)o*KTOT + kk*512 + i] = l;
    }
    float r2 = r*r;
    for (int i = tid; i < CIN; i += 256) {
        float s9 = 0.f;
#pragma unroll
        for (int k = 0; k < 9; k++) { float v = wo[i*9+k]; s9 += v*v; }
        g_W2[o*CIN+i] = s9*r2;
    }
}

// ============ K2: demod ============
__global__ void k2_demod() {
    int b = blockIdx.x, o = threadIdx.x;
    __shared__ float s2[CIN];
    float sv = g_styles[b*CIN+o];
    s2[o] = sv*sv; __syncthreads();
    const float* w2 = g_W2 + (size_t)o*CIN;
    float acc = 0.f;
    for (int i = 0; i < CIN; i++) acc += s2[i]*w2[i];
    g_d[b*COUT+o] = rsqrtf(acc + 1e-8f);
}

// ============ K_gemm: HMMA fp16 2-split implicit conv ============
// SMEM halfs per stage: Ah[128][40]=5120 | Al 5120 | Bh[32][136]=4352 | Bl 4352
#define SA_L 5120
#define SB_H 10240
#define STGH 18944                     // halfs per stage
#define GEMM_SMEM (2*STGH*2)           // 75776 bytes
#define NCH 144

__global__ __launch_bounds__(256)
void k_gemm(const float* __restrict__ cbias) {
    extern __shared__ __align__(16) char smraw[];
    uint32_t sb = smem_u32(smraw);
    int tid = threadIdx.x, w = tid >> 5, lane = tid & 31;
    int nt = blockIdx.x, oc0 = blockIdx.y * 128, bz = blockIdx.z;
    int wm = w & 1, wn = w >> 1;
    int m0 = wm * 64, n0 = wn * 32;

    // ---- per-thread load geometry ----
    int tl = tid & 127;
    int kloc = tl >> 2, asel = tl & 3;     // k-row 0..31, atom 0..3
    int hsel = tid >> 7;                   // pixel half 0/1; also A hi/lo select
    int atomB = nt*4 + asel;
    int pofs[8]; unsigned pval = 0;
#pragma unroll
    for (int i = 0; i < 8; i++) {
        int P, Q, j0 = hsel*16 + 2*i;
        if (atom_pix(atomB, j0, P, Q)) { pofs[i] = P*XPW + Q; pval |= (1u << i); }
        else pofs[i] = 0;
    }
    const __half* warr = hsel ? g_wl : g_wh;

    // ---- ldmatrix base offsets (bytes from stage base) ----
    uint32_t a_base = (uint32_t)(((m0 + (lane & 15))*40 + ((lane >> 4)*8)) * 2);
    uint32_t b_base = (uint32_t)((SB_H + ((lane & 7) + ((lane >> 3) & 1)*8)*136
                                  + n0 + ((lane >> 4)*8)) * 2);

    float acc[64];
#pragma unroll
    for (int t = 0; t < 64; t++) acc[t] = 0.f;

    uint32_t breg[16];

    auto loadA = [&](int ch, int st) {  // cp.async, 16B aligned everywhere
        const __half* src = warr + (size_t)(oc0 + tl)*KTOT + ch*32;
        uint32_t dst = sb + (uint32_t)((st*STGH + hsel*SA_L + tl*40) * 2);
        CP16(dst,      src);
        CP16(dst + 16, src + 8);
        CP16(dst + 32, src + 16);
        CP16(dst + 48, src + 24);
    };
    auto ldgB = [&](int ch) {           // packed u32 LDG, always 4B aligned
        int tap = ch >> 4, icb = (ch & 15) << 5;
        int sh = (tap/3)*XPW + (tap - (tap/3)*3);
        const uint32_t* xs = g_xhl + ((size_t)(bz*CIN + icb + kloc))*XPL + sh;
#pragma unroll
        for (int i = 0; i < 8; i++) {
            if ((pval >> i) & 1u) {
                breg[2*i]   = __ldg(xs + pofs[i]);
                breg[2*i+1] = __ldg(xs + pofs[i] + 1);
            } else { breg[2*i] = 0u; breg[2*i+1] = 0u; }
        }
    };
    auto stsB = [&](int st) {           // split + store hi/lo pairs
        uint32_t dh = sb + (uint32_t)((st*STGH + SB_H + kloc*136 + asel*32 + hsel*16) * 2);
#pragma unroll
        for (int i = 0; i < 8; i++) {
            uint32_t hp, lp;
            asm("prmt.b32 %0, %1, %2, 0x5410;" : "=r"(hp) : "r"(breg[2*i]), "r"(breg[2*i+1]));
            asm("prmt.b32 %0, %1, %2, 0x7632;" : "=r"(lp) : "r"(breg[2*i]), "r"(breg[2*i+1]));
            *(uint32_t*)(smraw + (dh - sb) + 4*i)        = hp;
            *(uint32_t*)(smraw + (dh - sb) + 8704 + 4*i) = lp;
        }
    };

    // prologue: fill stage 0
    ldgB(0);
    stsB(0);
    loadA(0, 0); CPC();
    asm volatile("cp.async.wait_group 0;");
    __syncthreads();

    for (int ch = 0; ch < NCH; ch++) {
        int st = ch & 1;
        if (ch + 1 < NCH) {
            ldgB(ch + 1);
            loadA(ch + 1, st ^ 1); CPC();
        }

        uint32_t sbase = sb + (uint32_t)(st * STGH * 2);
#pragma unroll
        for (int k16 = 0; k16 < 2; k16++) {
            uint32_t sA = sbase + a_base + k16*32;
            uint32_t sB = sbase + b_base + k16*(16*136*2);
            uint32_t ah[16], bh[8], bl[8];
#pragma unroll
            for (int mt = 0; mt < 4; mt++) LDSM4(&ah[mt*4], sA + mt*1280);
#pragma unroll
            for (int n2 = 0; n2 < 2; n2++) LDSM4T(&bh[n2*4], sB + n2*32);
#pragma unroll
            for (int mt = 0; mt < 4; mt++)
#pragma unroll
                for (int n = 0; n < 4; n++)
                    MMA(&acc[(mt*4+n)*4], &ah[mt*4],
                        bh[(n>>1)*4 + (n&1)*2], bh[(n>>1)*4 + (n&1)*2 + 1]);
#pragma unroll
            for (int n2 = 0; n2 < 2; n2++) LDSM4T(&bl[n2*4], sB + 8704 + n2*32);
#pragma unroll
            for (int mt = 0; mt < 4; mt++)
#pragma unroll
                for (int n = 0; n < 4; n++)
                    MMA(&acc[(mt*4+n)*4], &ah[mt*4],
                        bl[(n>>1)*4 + (n&1)*2], bl[(n>>1)*4 + (n&1)*2 + 1]);
#pragma unroll
            for (int mt = 0; mt < 4; mt++) LDSM4(&ah[mt*4], sA + 10240 + mt*1280);
#pragma unroll
            for (int mt = 0; mt < 4; mt++)
#pragma unroll
                for (int n = 0; n < 4; n++)
                    MMA(&acc[(mt*4+n)*4], &ah[mt*4],
                        bh[(n>>1)*4 + (n&1)*2], bh[(n>>1)*4 + (n&1)*2 + 1]);
        }

        if (ch + 1 < NCH) {
            asm volatile("cp.async.wait_group 0;");
            stsB(st ^ 1);
        }
        __syncthreads();
    }

    // ---- epilogue: demod + bias, float2 stores ----
#pragma unroll
    for (int mt = 0; mt < 4; mt++) {
        int ocA = oc0 + m0 + mt*16 + (lane >> 2);
        float dmA = g_d[bz*COUT + ocA],     biA = cbias[ocA];
        float dmB = g_d[bz*COUT + ocA + 8], biB = cbias[ocA + 8];
        size_t rowA = ((size_t)(bz*COUT + ocA)) * PLANE;
        size_t rowB = rowA + (size_t)8 * PLANE;
#pragma unroll
        for (int n = 0; n < 4; n++) {
            int nl = n0 + n*8 + (lane & 3)*2;
            int P, Q;
            if (!atom_pix(nt*4 + (nl >> 5), nl & 31, P, Q)) continue;
            int po = P*Y1S + Q;
            float* c = &acc[(mt*4+n)*4];
            *(float2*)(g_y1 + rowA + po) = make_float2(c[0]*dmA + biA, c[1]*dmA + biA);
            *(float2*)(g_y1 + rowB + po) = make_float2(c[2]*dmB + biB, c[3]*dmB + biB);
        }
    }
}

// ============ K4: fused upFIR -> lrelu/clamp -> downFIR ============
#define SM_VT  0
#define SM_ACT (138*66)
#define K4_FLOATS (138*66 + 138*139)
#define UTAPC(T, FI, LOADEXPR) { int n = rr + (T) - 9; if (n >= 0 && n < 132) { int jph = n >> 1; acc += (LOADEXPR)*fl[FI]; } }

__global__ __launch_bounds__(512)
void k4_fir(float* __restrict__ out) {
    int plane = blockIdx.x, tid = threadIdx.x;
    extern __shared__ float sm[];
    float* vt  = sm + SM_VT;
    float* act = sm + SM_ACT;
    const float* src = g_y1 + (size_t)plane*PLANE;
    float fl[12];
#pragma unroll
    for (int k = 0; k < 12; k++) fl[k] = g_filter[k];

    for (int e = tid; e < UPS*Y1S; e += 512) {
        int rr = e/Y1S, i = e - rr*Y1S;
        float acc = 0.f;
        if ((rr & 1) == 0) {
            UTAPC(1,10, src[jph*Y1S+i]); UTAPC(3,8, src[jph*Y1S+i]); UTAPC(5,6, src[jph*Y1S+i]);
            UTAPC(7,4, src[jph*Y1S+i]); UTAPC(9,2, src[jph*Y1S+i]); UTAPC(11,0, src[jph*Y1S+i]);
        } else {
            UTAPC(0,11, src[jph*Y1S+i]); UTAPC(2,9, src[jph*Y1S+i]); UTAPC(4,7, src[jph*Y1S+i]);
            UTAPC(6,5, src[jph*Y1S+i]); UTAPC(8,3, src[jph*Y1S+i]); UTAPC(10,1, src[jph*Y1S+i]);
        }
        vt[e] = 4.f*acc;
    }
    __syncthreads();
    for (int e = tid; e < UPS*UPS; e += 512) {
        int r = e/UPS, rr = e - r*UPS;
        const float* vr = vt + r*Y1S;
        float acc = 0.f;
        if ((rr & 1) == 0) {
            UTAPC(1,10, vr[jph]); UTAPC(3,8, vr[jph]); UTAPC(5,6, vr[jph]);
            UTAPC(7,4, vr[jph]); UTAPC(9,2, vr[jph]); UTAPC(11,0, vr[jph]);
        } else {
            UTAPC(0,11, vr[jph]); UTAPC(2,9, vr[jph]); UTAPC(4,7, vr[jph]);
            UTAPC(6,5, vr[jph]); UTAPC(8,3, vr[jph]); UTAPC(10,1, vr[jph]);
        }
        float a = (acc >= 0.f ? acc : 0.2f*acc)*1.4142135623730951f;
        act[r*139 + rr] = fminf(fmaxf(a, -256.f), 256.f);
    }
    __syncthreads();
    for (int e = tid; e < OUTS*UPS; e += 512) {
        int rr = e/UPS, j = e - rr*UPS;
        const float* ap = act + (2*rr)*139 + j;
        float acc = 0.f;
#pragma unroll
        for (int t = 0; t < 12; t++) acc += fl[11-t]*ap[t*139];
        vt[rr*UPS + j] = acc;
    }
    __syncthreads();
    float* dst = out + (size_t)plane*(OUTS*OUTS);
    for (int e = tid; e < OUTS*OUTS; e += 512) {
        int rr = e/OUTS, cc = e - rr*OUTS;
        const float* dp = vt + rr*UPS + 2*cc;
        float acc = 0.f;
#pragma unroll
        for (int t = 0; t < 12; t++) acc += fl[11-t]*dp[t];
        dst[rr*OUTS + cc] = acc;
    }
}

// ============ launch ============
extern "C" void kernel_launch(void* const* d_in, const int* in_sizes, int n_in,
                              void* d_out, int out_size) {
    const float* x  = (const float*)d_in[0];
    const float* w  = (const float*)d_in[1];
    const float* A  = (const float*)d_in[2];
    const float* ab = (const float*)d_in[3];
    const float* cw = (const float*)d_in[4];
    const float* cb = (const float*)d_in[5];
    float* out = (float*)d_out;

    cudaFuncSetAttribute(k_gemm, cudaFuncAttributeMaxDynamicSharedMemorySize, GEMM_SMEM);
    cudaFuncSetAttribute(k4_fir, cudaFuncAttributeMaxDynamicSharedMemorySize,
                         K4_FLOATS*(int)sizeof(float));

    k0_styles<<<1, 512>>>(w, A, ab);
    k1_wnorm<<<COUT, 256>>>(cw);
    k2_demod<<<BATCH, COUT>>>();
    k_pad<<<(BATCH*CIN*XPL + 255)/256, 256>>>(x);
    k_gemm<<<dim3(35, 4, BATCH), 256, GEMM_SMEM>>>(cb);
    k4_fir<<<BATCH*COUT, 512, K4_FLOATS*sizeof(float)>>>(out);
}

// round 7
// speedup vs baseline: 1.9981x; 1.2251x over previous
#include <cuda_runtime.h>
#include <cuda_fp16.h>
#include <cstdint>
#include <math.h>

#define BATCH 8
#define CIN   512
#define COUT  512
#define WDIM  512
#define INS   64
#define Y1S   66
#define PLANE 4356
#define UPS   138
#define OUTS  64
#define KTOT  4608
#define XPH   68
#define XPW   72
#define XPL   (XPH*XPW)   // 4896

__device__ float    g_styles[BATCH*CIN];
__device__ float    g_filter[12];
__device__ __half   g_wh[COUT*KTOT];
__device__ __half   g_wl[COUT*KTOT];
__device__ float    g_d[BATCH*COUT];
__device__ float    g_y1[BATCH*COUT*PLANE];
__device__ uint32_t g_xhl[BATCH*CIN*XPL];   // per pixel: (lo16<<16)|hi16

// ---------------- PTX helpers (sm_80-baseline only) ----------------
__device__ __forceinline__ uint32_t smem_u32(const void* p) {
    uint32_t a;
    asm("{ .reg .u64 t; cvta.to.shared.u64 t, %1; cvt.u32.u64 %0, t; }" : "=r"(a) : "l"(p));
    return a;
}
#define CP16(dst, src) \
    asm volatile("cp.async.cg.shared.global [%0], [%1], 16;" :: "r"(dst), "l"(src))
#define CPC() asm volatile("cp.async.commit_group;")
#define LDSM4(R, ad) \
    asm volatile("ldmatrix.sync.aligned.m8n8.x4.shared.b16 {%0,%1,%2,%3}, [%4];" \
        : "=r"((R)[0]), "=r"((R)[1]), "=r"((R)[2]), "=r"((R)[3]) : "r"(ad))
#define LDSM4T(R, ad) \
    asm volatile("ldmatrix.sync.aligned.m8n8.x4.trans.shared.b16 {%0,%1,%2,%3}, [%4];" \
        : "=r"((R)[0]), "=r"((R)[1]), "=r"((R)[2]), "=r"((R)[3]) : "r"(ad))
#define MMA(d, a, b0, b1) \
    asm volatile("mma.sync.aligned.m16n8k16.row.col.f32.f16.f16.f32 " \
        "{%0,%1,%2,%3}, {%4,%5,%6,%7}, {%8,%9}, {%0,%1,%2,%3};" \
        : "+f"((d)[0]), "+f"((d)[1]), "+f"((d)[2]), "+f"((d)[3]) \
        : "r"((a)[0]), "r"((a)[1]), "r"((a)[2]), "r"((a)[3]), "r"(b0), "r"(b1))

// atom(32px) -> plane pixel map; atoms 0..136 real. Pairs (j even, j+1) are
// always contiguous pixels and both-valid / both-invalid.
__device__ __forceinline__ bool atom_pix(int a, int j, int& P, int& Q) {
    if (a >= 137) return false;
    if (a < 132) {
        int blk = a / 33, ww = a - blk * 33;
        if (ww < 32) { P = blk*16 + (ww>>1); Q = ((ww&1)<<5) + j; return true; }
        P = blk*16 + (j>>1); Q = 64 + (j&1); return true;
    }
    if (a < 136) { int ww = a - 132; P = 64 + (ww>>1); Q = ((ww&1)<<5) + j; return true; }
    P = 64 + (j>>1); Q = 64 + (j&1); return (j < 4);
}
__device__ double bessel_i0(double x) {
    double t = x*x*0.25, term = 1.0, s = 1.0;
    for (int k = 1; k < 64; k++) { term *= t/((double)k*(double)k); s += term; if (term < 1e-18*s) break; }
    return s;
}
__device__ __forceinline__ void split2(float v, __half& h, __half& l) {
    h = __float2half_rn(v);
    l = __float2half_rn(v - __half2float(h));
}

// ============ K0: filter + styles + global style norm ============
__global__ void k0_styles(const float* __restrict__ w, const float* __restrict__ A,
                          const float* __restrict__ bias) {
    int i = threadIdx.x;
    if (i == 0) {
        const double PI = 3.14159265358979323846;
        double a = 2.285*11.0*PI*0.5 + 7.95;
        double beta = (a > 50.0) ? 0.1102*(a-8.7)
                     : (a > 21.0) ? 0.5842*pow(a-21.0,0.4)+0.07886*(a-21.0) : 0.0;
        double i0b = bessel_i0(beta), h[12], sum = 0.0;
        for (int n = 0; n < 12; n++) {
            double m = n - 5.5, sx = 0.5*m;
            double sinc = (sx==0.0) ? 1.0 : sin(PI*sx)/(PI*sx);
            double rt = m/5.5;
            h[n] = 0.5*sinc*bessel_i0(beta*sqrt(fmax(0.0,1.0-rt*rt)))/i0b;
            sum += h[n];
        }
        for (int n = 0; n < 12; n++) g_filter[n] = (float)(h[n]/sum);
    }
    float acc[BATCH];
#pragma unroll
    for (int b = 0; b < BATCH; b++) acc[b] = 0.f;
    const float* Ai = A + (size_t)i*WDIM;
    for (int k = 0; k < WDIM; k++) {
        float av = Ai[k];
#pragma unroll
        for (int b = 0; b < BATCH; b++) acc[b] += w[b*WDIM+k]*av;
    }
    float bi = bias[i], p = 0.f;
#pragma unroll
    for (int b = 0; b < BATCH; b++) { acc[b] = acc[b]*0.04419417382415922f + bi; p += acc[b]*acc[b]; }
    __shared__ float red[512];
    red[i] = p; __syncthreads();
    for (int s = 256; s > 0; s >>= 1) { if (i < s) red[i] += red[i+s]; __syncthreads(); }
    float sc = rsqrtf(red[0]*(1.0f/(BATCH*CIN)));
#pragma unroll
    for (int b = 0; b < BATCH; b++) g_styles[b*CIN+i] = acc[b]*sc;
}

// ============ K1: weight norm + fp16 split + demod (k2 folded in) ============
__global__ void k1_wnorm(const float* __restrict__ cw) {
    int o = blockIdx.x, tid = threadIdx.x;
    const float* wo = cw + (size_t)o*(CIN*9);
    __shared__ float red[256];
    float ss = 0.f;
    for (int t = tid; t < CIN*9; t += 256) { float v = wo[t]; ss += v*v; }
    red[tid] = ss; __syncthreads();
    for (int s = 128; s > 0; s >>= 1) { if (tid < s) red[tid] += red[tid+s]; __syncthreads(); }
    float r = rsqrtf(red[0]*(1.0f/(CIN*9)));
    __syncthreads();
    for (int t = tid; t < CIN*9; t += 256) {
        int i = t/9, kk = t - i*9;
        __half h, l; split2(wo[t]*r, h, l);
        g_wh[(size_t)o*KTOT + kk*512 + i] = h;
        g_wl[(size_t)o*KTOT + kk*512 + i] = l;
    }
    // demod: dm[b] = rsqrt( sum_i s[b][i]^2 * w2[i] + 1e-8 )
    float r2 = r*r;
    float part[BATCH];
#pragma unroll
    for (int b = 0; b < BATCH; b++) part[b] = 0.f;
    for (int i = tid; i < CIN; i += 256) {
        float s9 = 0.f;
#pragma unroll
        for (int k = 0; k < 9; k++) { float v = wo[i*9+k]; s9 += v*v; }
        float w2 = s9*r2;
#pragma unroll
        for (int b = 0; b < BATCH; b++) {
            float sv = g_styles[b*CIN+i];
            part[b] += sv*sv*w2;
        }
    }
#pragma unroll
    for (int b = 0; b < BATCH; b++) {
        red[tid] = part[b]; __syncthreads();
        for (int s = 128; s > 0; s >>= 1) { if (tid < s) red[tid] += red[tid+s]; __syncthreads(); }
        if (tid == 0) g_d[b*COUT+o] = rsqrtf(red[0] + 1e-8f);
        __syncthreads();
    }
}

// ============ K_pad: padded style-scaled packed fp16-split input ============
__global__ void k_pad(const float* __restrict__ x) {
    int idx = blockIdx.x*256 + threadIdx.x;
    if (idx >= BATCH*CIN*XPL) return;
    int col = idx % XPW, row = (idx/XPW) % XPH;
    int c = (idx/XPL) % CIN, b = idx/(XPL*CIN);
    int ri = row - 2, ci = col - 2;
    float v = 0.f;
    if (ri >= 0 && ri < INS && ci >= 0 && ci < INS)
        v = x[(((size_t)b*CIN+c)*INS+ri)*INS+ci] * g_styles[b*CIN+c];
    __half h, l; split2(v, h, l);
    g_xhl[idx] = ((uint32_t)__half_as_ushort(l) << 16) | (uint32_t)__half_as_ushort(h);
}

// ============ K_gemm: HMMA fp16 2-split implicit conv ============
// SMEM halfs per stage: Ah[128][40]=5120 | Al 5120 | Bh[32][136]=4352 | Bl 4352
#define SA_L 5120
#define SB_H 10240
#define STGH 18944                     // halfs per stage
#define GEMM_SMEM (2*STGH*2)           // 75776 bytes
#define NCH 144

__global__ __launch_bounds__(256, 2)
void k_gemm(const float* __restrict__ cbias) {
    extern __shared__ __align__(16) char smraw[];
    uint32_t sb = smem_u32(smraw);
    int tid = threadIdx.x, w = tid >> 5, lane = tid & 31;
    int nt = blockIdx.x, oc0 = blockIdx.y * 128, bz = blockIdx.z;
    int wm = w & 1, wn = w >> 1;
    int m0 = wm * 64, n0 = wn * 32;

    // ---- per-thread load geometry ----
    int tl = tid & 127;
    int kloc = tl >> 2, asel = tl & 3;     // k-row 0..31, atom 0..3
    int hsel = tid >> 7;                   // pixel half 0/1; also A hi/lo select
    int atomB = nt*4 + asel;
    int pofs[8]; unsigned pval = 0;
#pragma unroll
    for (int i = 0; i < 8; i++) {
        int P, Q, j0 = hsel*16 + 2*i;
        if (atom_pix(atomB, j0, P, Q)) { pofs[i] = P*XPW + Q; pval |= (1u << i); }
        else pofs[i] = 0;
    }
    const __half* warr = hsel ? g_wl : g_wh;

    // ---- ldmatrix base offsets (bytes from stage base) ----
    uint32_t a_base = (uint32_t)(((m0 + (lane & 15))*40 + ((lane >> 4)*8)) * 2);
    uint32_t b_base = (uint32_t)((SB_H + ((lane & 7) + ((lane >> 3) & 1)*8)*136
                                  + n0 + ((lane >> 4)*8)) * 2);

    float acc[64];
#pragma unroll
    for (int t = 0; t < 64; t++) acc[t] = 0.f;

    uint32_t breg[16];

    auto loadA = [&](int ch, int st) {  // cp.async, 16B aligned everywhere
        const __half* src = warr + (size_t)(oc0 + tl)*KTOT + ch*32;
        uint32_t dst = sb + (uint32_t)((st*STGH + hsel*SA_L + tl*40) * 2);
        CP16(dst,      src);
        CP16(dst + 16, src + 8);
        CP16(dst + 32, src + 16);
        CP16(dst + 48, src + 24);
    };
    auto ldgB = [&](int ch) {           // packed u32 LDG, always 4B aligned
        int tap = ch >> 4, icb = (ch & 15) << 5;
        int sh = (tap/3)*XPW + (tap - (tap/3)*3);
        const uint32_t* xs = g_xhl + ((size_t)(bz*CIN + icb + kloc))*XPL + sh;
#pragma unroll
        for (int i = 0; i < 8; i++) {
            if ((pval >> i) & 1u) {
                breg[2*i]   = __ldg(xs + pofs[i]);
                breg[2*i+1] = __ldg(xs + pofs[i] + 1);
            } else { breg[2*i] = 0u; breg[2*i+1] = 0u; }
        }
    };
    auto stsB = [&](int st) {           // split + store hi/lo pairs
        uint32_t base = (uint32_t)((st*STGH + SB_H + kloc*136 + asel*32 + hsel*16) * 2);
#pragma unroll
        for (int i = 0; i < 8; i++) {
            uint32_t hp, lp;
            asm("prmt.b32 %0, %1, %2, 0x5410;" : "=r"(hp) : "r"(breg[2*i]), "r"(breg[2*i+1]));
            asm("prmt.b32 %0, %1, %2, 0x7632;" : "=r"(lp) : "r"(breg[2*i]), "r"(breg[2*i+1]));
            *(uint32_t*)(smraw + base + 4*i)        = hp;
            *(uint32_t*)(smraw + base + 8704 + 4*i) = lp;
        }
    };

    // prologue: fill stage 0
    ldgB(0);
    stsB(0);
    loadA(0, 0); CPC();
    asm volatile("cp.async.wait_group 0;");
    __syncthreads();

    for (int ch = 0; ch < NCH; ch++) {
        int st = ch & 1;
        if (ch + 1 < NCH) {
            ldgB(ch + 1);
            loadA(ch + 1, st ^ 1); CPC();
        }

        uint32_t sbase = sb + (uint32_t)(st * STGH * 2);
#pragma unroll
        for (int k16 = 0; k16 < 2; k16++) {
            uint32_t sA = sbase + a_base + k16*32;
            uint32_t sB = sbase + b_base + k16*(16*136*2);
            uint32_t ah[16], bh[8], bl[8];
#pragma unroll
            for (int mt = 0; mt < 4; mt++) LDSM4(&ah[mt*4], sA + mt*1280);
#pragma unroll
            for (int n2 = 0; n2 < 2; n2++) LDSM4T(&bh[n2*4], sB + n2*32);
#pragma unroll
            for (int mt = 0; mt < 4; mt++)
#pragma unroll
                for (int n = 0; n < 4; n++)
                    MMA(&acc[(mt*4+n)*4], &ah[mt*4],
                        bh[(n>>1)*4 + (n&1)*2], bh[(n>>1)*4 + (n&1)*2 + 1]);
#pragma unroll
            for (int n2 = 0; n2 < 2; n2++) LDSM4T(&bl[n2*4], sB + 8704 + n2*32);
#pragma unroll
            for (int mt = 0; mt < 4; mt++)
#pragma unroll
                for (int n = 0; n < 4; n++)
                    MMA(&acc[(mt*4+n)*4], &ah[mt*4],
                        bl[(n>>1)*4 + (n&1)*2], bl[(n>>1)*4 + (n&1)*2 + 1]);
#pragma unroll
            for (int mt = 0; mt < 4; mt++) LDSM4(&ah[mt*4], sA + 10240 + mt*1280);
#pragma unroll
            for (int mt = 0; mt < 4; mt++)
#pragma unroll
                for (int n = 0; n < 4; n++)
                    MMA(&acc[(mt*4+n)*4], &ah[mt*4],
                        bh[(n>>1)*4 + (n&1)*2], bh[(n>>1)*4 + (n&1)*2 + 1]);
        }

        if (ch + 1 < NCH) {
            asm volatile("cp.async.wait_group 0;");
            stsB(st ^ 1);
        }
        __syncthreads();
    }

    // ---- epilogue: demod + bias, float2 stores ----
#pragma unroll
    for (int mt = 0; mt < 4; mt++) {
        int ocA = oc0 + m0 + mt*16 + (lane >> 2);
        float dmA = g_d[bz*COUT + ocA],     biA = cbias[ocA];
        float dmB = g_d[bz*COUT + ocA + 8], biB = cbias[ocA + 8];
        size_t rowA = ((size_t)(bz*COUT + ocA)) * PLANE;
        size_t rowB = rowA + (size_t)8 * PLANE;
#pragma unroll
        for (int n = 0; n < 4; n++) {
            int nl = n0 + n*8 + (lane & 3)*2;
            int P, Q;
            if (!atom_pix(nt*4 + (nl >> 5), nl & 31, P, Q)) continue;
            int po = P*Y1S + Q;
            float* c = &acc[(mt*4+n)*4];
            *(float2*)(g_y1 + rowA + po) = make_float2(c[0]*dmA + biA, c[1]*dmA + biA);
            *(float2*)(g_y1 + rowB + po) = make_float2(c[2]*dmB + biB, c[3]*dmB + biB);
        }
    }
}

// ============ K4: fused upFIR -> lrelu/clamp -> downFIR ============
#define SM_VT  0
#define SM_ACT (138*66)
#define K4_FLOATS (138*66 + 138*139)
#define UTAPC(T, FI, LOADEXPR) { int n = rr + (T) - 9; if (n >= 0 && n < 132) { int jph = n >> 1; acc += (LOADEXPR)*fl[FI]; } }

__global__ __launch_bounds__(512)
void k4_fir(float* __restrict__ out) {
    int plane = blockIdx.x, tid = threadIdx.x;
    extern __shared__ float sm[];
    float* vt  = sm + SM_VT;
    float* act = sm + SM_ACT;
    const float* src = g_y1 + (size_t)plane*PLANE;
    float fl[12];
#pragma unroll
    for (int k = 0; k < 12; k++) fl[k] = g_filter[k];

    for (int e = tid; e < UPS*Y1S; e += 512) {
        int rr = e/Y1S, i = e - rr*Y1S;
        float acc = 0.f;
        if ((rr & 1) == 0) {
            UTAPC(1,10, src[jph*Y1S+i]); UTAPC(3,8, src[jph*Y1S+i]); UTAPC(5,6, src[jph*Y1S+i]);
            UTAPC(7,4, src[jph*Y1S+i]); UTAPC(9,2, src[jph*Y1S+i]); UTAPC(11,0, src[jph*Y1S+i]);
        } else {
            UTAPC(0,11, src[jph*Y1S+i]); UTAPC(2,9, src[jph*Y1S+i]); UTAPC(4,7, src[jph*Y1S+i]);
            UTAPC(6,5, src[jph*Y1S+i]); UTAPC(8,3, src[jph*Y1S+i]); UTAPC(10,1, src[jph*Y1S+i]);
        }
        vt[e] = 4.f*acc;
    }
    __syncthreads();
    for (int e = tid; e < UPS*UPS; e += 512) {
        int r = e/UPS, rr = e - r*UPS;
        const float* vr = vt + r*Y1S;
        float acc = 0.f;
        if ((rr & 1) == 0) {
            UTAPC(1,10, vr[jph]); UTAPC(3,8, vr[jph]); UTAPC(5,6, vr[jph]);
            UTAPC(7,4, vr[jph]); UTAPC(9,2, vr[jph]); UTAPC(11,0, vr[jph]);
        } else {
            UTAPC(0,11, vr[jph]); UTAPC(2,9, vr[jph]); UTAPC(4,7, vr[jph]);
            UTAPC(6,5, vr[jph]); UTAPC(8,3, vr[jph]); UTAPC(10,1, vr[jph]);
        }
        float a = (acc >= 0.f ? acc : 0.2f*acc)*1.4142135623730951f;
        act[r*139 + rr] = fminf(fmaxf(a, -256.f), 256.f);
    }
    __syncthreads();
    for (int e = tid; e < OUTS*UPS; e += 512) {
        int rr = e/UPS, j = e - rr*UPS;
        const float* ap = act + (2*rr)*139 + j;
        float acc = 0.f;
#pragma unroll
        for (int t = 0; t < 12; t++) acc += fl[11-t]*ap[t*139];
        vt[rr*UPS + j] = acc;
    }
    __syncthreads();
    float* dst = out + (size_t)plane*(OUTS*OUTS);
    for (int e = tid; e < OUTS*OUTS; e += 512) {
        int rr = e/OUTS, cc = e - rr*OUTS;
        const float* dp = vt + rr*UPS + 2*cc;
        float acc = 0.f;
#pragma unroll
        for (int t = 0; t < 12; t++) acc += fl[11-t]*dp[t];
        dst[rr*OUTS + cc] = acc;
    }
}

// ============ launch ============
extern "C" void kernel_launch(void* const* d_in, const int* in_sizes, int n_in,
                              void* d_out, int out_size) {
    const float* x  = (const float*)d_in[0];
    const float* w  = (const float*)d_in[1];
    const float* A  = (const float*)d_in[2];
    const float* ab = (const float*)d_in[3];
    const float* cw = (const float*)d_in[4];
    const float* cb = (const float*)d_in[5];
    float* out = (float*)d_out;

    cudaFuncSetAttribute(k_gemm, cudaFuncAttributeMaxDynamicSharedMemorySize, GEMM_SMEM);
    cudaFuncSetAttribute(k4_fir, cudaFuncAttributeMaxDynamicSharedMemorySize,
                         K4_FLOATS*(int)sizeof(float));

    k0_styles<<<1, 512>>>(w, A, ab);
    k1_wnorm<<<COUT, 256>>>(cw);
    k_pad<<<(BATCH*CIN*XPL + 255)/256, 256>>>(x);
    k_gemm<<<dim3(35, 4, BATCH), 256, GEMM_SMEM>>>(cb);   // launch idx 3
    k4_fir<<<BATCH*COUT, 512, K4_FLOATS*sizeof(float)>>>(out);
}

// round 8
// speedup vs baseline: 2.5850x; 1.2937x over previous
#include <cuda_runtime.h>
#include <cuda_fp16.h>
#include <cstdint>
#include <math.h>

#define BATCH 8
#define CIN   512
#define COUT  512
#define WDIM  512
#define INS   64
#define Y1S   66
#define PLANE 4356
#define UPS   138
#define OUTS  64
#define KTOT  4608
#define XPH   68
#define XPW   72
#define XPL   (XPH*XPW)   // 4896

__device__ float    g_styles[BATCH*CIN];
__device__ float    g_filter[12];
__device__ __half   g_wh[COUT*KTOT];
__device__ __half   g_wl[COUT*KTOT];
__device__ float    g_d[BATCH*COUT];
__device__ float    g_y1[BATCH*COUT*PLANE];
__device__ uint32_t g_xhl[BATCH*CIN*XPL];   // per pixel: (lo16<<16)|hi16

// ---------------- PTX helpers (sm_80-baseline only) ----------------
__device__ __forceinline__ uint32_t smem_u32(const void* p) {
    uint32_t a;
    asm("{ .reg .u64 t; cvta.to.shared.u64 t, %1; cvt.u32.u64 %0, t; }" : "=r"(a) : "l"(p));
    return a;
}
#define CP16(dst, src) \
    asm volatile("cp.async.cg.shared.global [%0], [%1], 16;" :: "r"(dst), "l"(src))
#define CPC() asm volatile("cp.async.commit_group;")
#define LDSM4(R, ad) \
    asm volatile("ldmatrix.sync.aligned.m8n8.x4.shared.b16 {%0,%1,%2,%3}, [%4];" \
        : "=r"((R)[0]), "=r"((R)[1]), "=r"((R)[2]), "=r"((R)[3]) : "r"(ad))
#define LDSM4T(R, ad) \
    asm volatile("ldmatrix.sync.aligned.m8n8.x4.trans.shared.b16 {%0,%1,%2,%3}, [%4];" \
        : "=r"((R)[0]), "=r"((R)[1]), "=r"((R)[2]), "=r"((R)[3]) : "r"(ad))
#define MMA(d, a, b0, b1) \
    asm volatile("mma.sync.aligned.m16n8k16.row.col.f32.f16.f16.f32 " \
        "{%0,%1,%2,%3}, {%4,%5,%6,%7}, {%8,%9}, {%0,%1,%2,%3};" \
        : "+f"((d)[0]), "+f"((d)[1]), "+f"((d)[2]), "+f"((d)[3]) \
        : "r"((a)[0]), "r"((a)[1]), "r"((a)[2]), "r"((a)[3]), "r"(b0), "r"(b1))

// atom(32px) -> plane pixel map; atoms 0..136 real. For a%33!=32 and a<136 the
// 32 pixels of an atom are CONTIGUOUS in the plane row (coalesced loads).
__device__ __forceinline__ bool atom_pix(int a, int j, int& P, int& Q) {
    if (a >= 137) return false;
    if (a < 132) {
        int blk = a / 33, ww = a - blk * 33;
        if (ww < 32) { P = blk*16 + (ww>>1); Q = ((ww&1)<<5) + j; return true; }
        P = blk*16 + (j>>1); Q = 64 + (j&1); return true;
    }
    if (a < 136) { int ww = a - 132; P = 64 + (ww>>1); Q = ((ww&1)<<5) + j; return true; }
    P = 64 + (j>>1); Q = 64 + (j&1); return (j < 4);
}
__device__ double bessel_i0(double x) {
    double t = x*x*0.25, term = 1.0, s = 1.0;
    for (int k = 1; k < 64; k++) { term *= t/((double)k*(double)k); s += term; if (term < 1e-18*s) break; }
    return s;
}
__device__ __forceinline__ void split2(float v, __half& h, __half& l) {
    h = __float2half_rn(v);
    l = __float2half_rn(v - __half2float(h));
}

// ============ K0: filter + styles + global style norm ============
__global__ void k0_styles(const float* __restrict__ w, const float* __restrict__ A,
                          const float* __restrict__ bias) {
    int i = threadIdx.x;
    if (i == 0) {
        const double PI = 3.14159265358979323846;
        double a = 2.285*11.0*PI*0.5 + 7.95;
        double beta = (a > 50.0) ? 0.1102*(a-8.7)
                     : (a > 21.0) ? 0.5842*pow(a-21.0,0.4)+0.07886*(a-21.0) : 0.0;
        double i0b = bessel_i0(beta), h[12], sum = 0.0;
        for (int n = 0; n < 12; n++) {
            double m = n - 5.5, sx = 0.5*m;
            double sinc = (sx==0.0) ? 1.0 : sin(PI*sx)/(PI*sx);
            double rt = m/5.5;
            h[n] = 0.5*sinc*bessel_i0(beta*sqrt(fmax(0.0,1.0-rt*rt)))/i0b;
            sum += h[n];
        }
        for (int n = 0; n < 12; n++) g_filter[n] = (float)(h[n]/sum);
    }
    float acc[BATCH];
#pragma unroll
    for (int b = 0; b < BATCH; b++) acc[b] = 0.f;
    const float* Ai = A + (size_t)i*WDIM;
    for (int k = 0; k < WDIM; k++) {
        float av = Ai[k];
#pragma unroll
        for (int b = 0; b < BATCH; b++) acc[b] += w[b*WDIM+k]*av;
    }
    float bi = bias[i], p = 0.f;
#pragma unroll
    for (int b = 0; b < BATCH; b++) { acc[b] = acc[b]*0.04419417382415922f + bi; p += acc[b]*acc[b]; }
    __shared__ float red[512];
    red[i] = p; __syncthreads();
    for (int s = 256; s > 0; s >>= 1) { if (i < s) red[i] += red[i+s]; __syncthreads(); }
    float sc = rsqrtf(red[0]*(1.0f/(BATCH*CIN)));
#pragma unroll
    for (int b = 0; b < BATCH; b++) g_styles[b*CIN+i] = acc[b]*sc;
}

// ============ K1: weight norm + fp16 split + demod ============
__global__ void k1_wnorm(const float* __restrict__ cw) {
    int o = blockIdx.x, tid = threadIdx.x;
    const float* wo = cw + (size_t)o*(CIN*9);
    __shared__ float red[256];
    float ss = 0.f;
    for (int t = tid; t < CIN*9; t += 256) { float v = wo[t]; ss += v*v; }
    red[tid] = ss; __syncthreads();
    for (int s = 128; s > 0; s >>= 1) { if (tid < s) red[tid] += red[tid+s]; __syncthreads(); }
    float r = rsqrtf(red[0]*(1.0f/(CIN*9)));
    __syncthreads();
    for (int t = tid; t < CIN*9; t += 256) {
        int i = t/9, kk = t - i*9;
        __half h, l; split2(wo[t]*r, h, l);
        g_wh[(size_t)o*KTOT + kk*512 + i] = h;
        g_wl[(size_t)o*KTOT + kk*512 + i] = l;
    }
    float r2 = r*r;
    float part[BATCH];
#pragma unroll
    for (int b = 0; b < BATCH; b++) part[b] = 0.f;
    for (int i = tid; i < CIN; i += 256) {
        float s9 = 0.f;
#pragma unroll
        for (int k = 0; k < 9; k++) { float v = wo[i*9+k]; s9 += v*v; }
        float w2 = s9*r2;
#pragma unroll
        for (int b = 0; b < BATCH; b++) {
            float sv = g_styles[b*CIN+i];
            part[b] += sv*sv*w2;
        }
    }
#pragma unroll
    for (int b = 0; b < BATCH; b++) {
        red[tid] = part[b]; __syncthreads();
        for (int s = 128; s > 0; s >>= 1) { if (tid < s) red[tid] += red[tid+s]; __syncthreads(); }
        if (tid == 0) g_d[b*COUT+o] = rsqrtf(red[0] + 1e-8f);
        __syncthreads();
    }
}

// ============ K_pad: padded style-scaled packed fp16-split input ============
__global__ void k_pad(const float* __restrict__ x) {
    int idx = blockIdx.x*256 + threadIdx.x;
    if (idx >= BATCH*CIN*XPL) return;
    int col = idx % XPW, row = (idx/XPW) % XPH;
    int c = (idx/XPL) % CIN, b = idx/(XPL*CIN);
    int ri = row - 2, ci = col - 2;
    float v = 0.f;
    if (ri >= 0 && ri < INS && ci >= 0 && ci < INS)
        v = x[(((size_t)b*CIN+c)*INS+ri)*INS+ci] * g_styles[b*CIN+c];
    __half h, l; split2(v, h, l);
    g_xhl[idx] = ((uint32_t)__half_as_ushort(l) << 16) | (uint32_t)__half_as_ushort(h);
}

// ============ K_gemm: HMMA fp16 2-split implicit conv ============
// SMEM halfs per stage: Ah[128][40]=5120 | Al 5120 | Bh[32][136]=4352 | Bl 4352
#define SA_L 5120
#define SB_H 10240
#define STGH 18944                     // halfs per stage
#define GEMM_SMEM (2*STGH*2)           // 75776 bytes
#define NCH 144

__global__ __launch_bounds__(256, 2)
void k_gemm(const float* __restrict__ cbias) {
    extern __shared__ __align__(16) char smraw[];
    uint32_t sb = smem_u32(smraw);
    int tid = threadIdx.x, w = tid >> 5, lane = tid & 31;
    int nt = blockIdx.x, oc0 = blockIdx.y * 128, bz = blockIdx.z;
    int wm = w & 1, wn = w >> 1;
    int m0 = wm * 64, n0 = wn * 32;

    // ---- B geometry: per-lane pixel offset for each of the 4 atoms.
    // warp w loads channels [4w,4w+4) x atoms 0..3; lane = pixel-in-atom.
    // For contiguous atoms lanes read consecutive u32 -> fully coalesced LDG.
    int pofs[4]; unsigned pv = 0;
#pragma unroll
    for (int t = 0; t < 4; t++) {
        int P, Q;
        if (atom_pix(nt*4 + t, lane, P, Q)) { pofs[t] = P*XPW + Q; pv |= (1u << t); }
        else pofs[t] = 0;
    }

    // ---- A-load geometry (unchanged) ----
    int tl = tid & 127;
    int hsel = tid >> 7;                   // A hi/lo select
    const __half* warr = hsel ? g_wl : g_wh;

    // ---- ldmatrix base offsets (bytes from stage base) ----
    uint32_t a_base = (uint32_t)(((m0 + (lane & 15))*40 + ((lane >> 4)*8)) * 2);
    uint32_t b_base = (uint32_t)((SB_H + ((lane & 7) + ((lane >> 3) & 1)*8)*136
                                  + n0 + ((lane >> 4)*8)) * 2);

    float acc[64];
#pragma unroll
    for (int t = 0; t < 64; t++) acc[t] = 0.f;

    uint32_t breg[16];

    auto loadA = [&](int ch, int st) {  // cp.async, 16B aligned everywhere
        const __half* src = warr + (size_t)(oc0 + tl)*KTOT + ch*32;
        uint32_t dst = sb + (uint32_t)((st*STGH + hsel*SA_L + tl*40) * 2);
        CP16(dst,      src);
        CP16(dst + 16, src + 8);
        CP16(dst + 32, src + 16);
        CP16(dst + 48, src + 24);
    };
    auto ldgB = [&](int ch) {           // coalesced u32 LDG per (channel,atom) row
        int tap = ch >> 4, icb = (ch & 15) << 5;
        int sh = (tap/3)*XPW + (tap - (tap/3)*3);
        const uint32_t* xs = g_xhl + (size_t)bz*(CIN*XPL) + (size_t)(icb + w*4)*XPL + sh;
#pragma unroll
        for (int i = 0; i < 16; i++) {
            int k = i >> 2, a = i & 3;   // channel w*4+k, atom a
            breg[i] = ((pv >> a) & 1u) ? __ldg(xs + (size_t)k*XPL + pofs[a]) : 0u;
        }
    };
    auto stsB = [&](int st) {           // split each pixel u32 -> Bh/Bl halves
        uint32_t base = (uint32_t)((st*STGH + SB_H) * 2);
#pragma unroll
        for (int i = 0; i < 16; i++) {
            int k = (w << 2) + (i >> 2), a = i & 3;
            uint32_t idx = (uint32_t)((k*136 + a*32 + lane) * 2);
            *(unsigned short*)(smraw + base + idx)        = (unsigned short)(breg[i] & 0xFFFF);
            *(unsigned short*)(smraw + base + 8704 + idx) = (unsigned short)(breg[i] >> 16);
        }
    };

    // prologue: fill stage 0
    ldgB(0);
    stsB(0);
    loadA(0, 0); CPC();
    asm volatile("cp.async.wait_group 0;");
    __syncthreads();

    for (int ch = 0; ch < NCH; ch++) {
        int st = ch & 1;
        if (ch + 1 < NCH) {
            ldgB(ch + 1);
            loadA(ch + 1, st ^ 1); CPC();
        }

        uint32_t sbase = sb + (uint32_t)(st * STGH * 2);
#pragma unroll
        for (int k16 = 0; k16 < 2; k16++) {
            uint32_t sA = sbase + a_base + k16*32;
            uint32_t sB = sbase + b_base + k16*(16*136*2);
            uint32_t ah[16], bh[8], bl[8];
#pragma unroll
            for (int mt = 0; mt < 4; mt++) LDSM4(&ah[mt*4], sA + mt*1280);
#pragma unroll
            for (int n2 = 0; n2 < 2; n2++) LDSM4T(&bh[n2*4], sB + n2*32);
#pragma unroll
            for (int mt = 0; mt < 4; mt++)
#pragma unroll
                for (int n = 0; n < 4; n++)
                    MMA(&acc[(mt*4+n)*4], &ah[mt*4],
                        bh[(n>>1)*4 + (n&1)*2], bh[(n>>1)*4 + (n&1)*2 + 1]);
#pragma unroll
            for (int n2 = 0; n2 < 2; n2++) LDSM4T(&bl[n2*4], sB + 8704 + n2*32);
#pragma unroll
            for (int mt = 0; mt < 4; mt++)
#pragma unroll
                for (int n = 0; n < 4; n++)
                    MMA(&acc[(mt*4+n)*4], &ah[mt*4],
                        bl[(n>>1)*4 + (n&1)*2], bl[(n>>1)*4 + (n&1)*2 + 1]);
#pragma unroll
            for (int mt = 0; mt < 4; mt++) LDSM4(&ah[mt*4], sA + 10240 + mt*1280);
#pragma unroll
            for (int mt = 0; mt < 4; mt++)
#pragma unroll
                for (int n = 0; n < 4; n++)
                    MMA(&acc[(mt*4+n)*4], &ah[mt*4],
                        bh[(n>>1)*4 + (n&1)*2], bh[(n>>1)*4 + (n&1)*2 + 1]);
        }

        if (ch + 1 < NCH) {
            asm volatile("cp.async.wait_group 0;");
            stsB(st ^ 1);
        }
        __syncthreads();
    }

    // ---- epilogue: demod + bias, float2 stores ----
#pragma unroll
    for (int mt = 0; mt < 4; mt++) {
        int ocA = oc0 + m0 + mt*16 + (lane >> 2);
        float dmA = g_d[bz*COUT + ocA],     biA = cbias[ocA];
        float dmB = g_d[bz*COUT + ocA + 8], biB = cbias[ocA + 8];
        size_t rowA = ((size_t)(bz*COUT + ocA)) * PLANE;
        size_t rowB = rowA + (size_t)8 * PLANE;
#pragma unroll
        for (int n = 0; n < 4; n++) {
            int nl = n0 + n*8 + (lane & 3)*2;
            int P, Q;
            if (!atom_pix(nt*4 + (nl >> 5), nl & 31, P, Q)) continue;
            int po = P*Y1S + Q;
            float* c = &acc[(mt*4+n)*4];
            *(float2*)(g_y1 + rowA + po) = make_float2(c[0]*dmA + biA, c[1]*dmA + biA);
            *(float2*)(g_y1 + rowB + po) = make_float2(c[2]*dmB + biB, c[3]*dmB + biB);
        }
    }
}

// ============ K4: fused upFIR -> lrelu/clamp -> downFIR ============
#define SM_VT  0
#define SM_ACT (138*66)
#define K4_FLOATS (138*66 + 138*139)
#define UTAPC(T, FI, LOADEXPR) { int n = rr + (T) - 9; if (n >= 0 && n < 132) { int jph = n >> 1; acc += (LOADEXPR)*fl[FI]; } }

__global__ __launch_bounds__(512)
void k4_fir(float* __restrict__ out) {
    int plane = blockIdx.x, tid = threadIdx.x;
    extern __shared__ float sm[];
    float* vt  = sm + SM_VT;
    float* act = sm + SM_ACT;
    const float* src = g_y1 + (size_t)plane*PLANE;
    float fl[12];
#pragma unroll
    for (int k = 0; k < 12; k++) fl[k] = g_filter[k];

    for (int e = tid; e < UPS*Y1S; e += 512) {
        int rr = e/Y1S, i = e - rr*Y1S;
        float acc = 0.f;
        if ((rr & 1) == 0) {
            UTAPC(1,10, src[jph*Y1S+i]); UTAPC(3,8, src[jph*Y1S+i]); UTAPC(5,6, src[jph*Y1S+i]);
            UTAPC(7,4, src[jph*Y1S+i]); UTAPC(9,2, src[jph*Y1S+i]); UTAPC(11,0, src[jph*Y1S+i]);
        } else {
            UTAPC(0,11, src[jph*Y1S+i]); UTAPC(2,9, src[jph*Y1S+i]); UTAPC(4,7, src[jph*Y1S+i]);
            UTAPC(6,5, src[jph*Y1S+i]); UTAPC(8,3, src[jph*Y1S+i]); UTAPC(10,1, src[jph*Y1S+i]);
        }
        vt[e] = 4.f*acc;
    }
    __syncthreads();
    for (int e = tid; e < UPS*UPS; e += 512) {
        int r = e/UPS, rr = e - r*UPS;
        const float* vr = vt + r*Y1S;
        float acc = 0.f;
        if ((rr & 1) == 0) {
            UTAPC(1,10, vr[jph]); UTAPC(3,8, vr[jph]); UTAPC(5,6, vr[jph]);
            UTAPC(7,4, vr[jph]); UTAPC(9,2, vr[jph]); UTAPC(11,0, vr[jph]);
        } else {
            UTAPC(0,11, vr[jph]); UTAPC(2,9, vr[jph]); UTAPC(4,7, vr[jph]);
            UTAPC(6,5, vr[jph]); UTAPC(8,3, vr[jph]); UTAPC(10,1, vr[jph]);
        }
        float a = (acc >= 0.f ? acc : 0.2f*acc)*1.4142135623730951f;
        act[r*139 + rr] = fminf(fmaxf(a, -256.f), 256.f);
    }
    __syncthreads();
    for (int e = tid; e < OUTS*UPS; e += 512) {
        int rr = e/UPS, j = e - rr*UPS;
        const float* ap = act + (2*rr)*139 + j;
        float acc = 0.f;
#pragma unroll
        for (int t = 0; t < 12; t++) acc += fl[11-t]*ap[t*139];
        vt[rr*UPS + j] = acc;
    }
    __syncthreads();
    float* dst = out + (size_t)plane*(OUTS*OUTS);
    for (int e = tid; e < OUTS*OUTS; e += 512) {
        int rr = e/OUTS, cc = e - rr*OUTS;
        const float* dp = vt + rr*UPS + 2*cc;
        float acc = 0.f;
#pragma unroll
        for (int t = 0; t < 12; t++) acc += fl[11-t]*dp[t];
        dst[rr*OUTS + cc] = acc;
    }
}

// ============ launch ============
extern "C" void kernel_launch(void* const* d_in, const int* in_sizes, int n_in,
                              void* d_out, int out_size) {
    const float* x  = (const float*)d_in[0];
    const float* w  = (const float*)d_in[1];
    const float* A  = (const float*)d_in[2];
    const float* ab = (const float*)d_in[3];
    const float* cw = (const float*)d_in[4];
    const float* cb = (const float*)d_in[5];
    float* out = (float*)d_out;

    cudaFuncSetAttribute(k_gemm, cudaFuncAttributeMaxDynamicSharedMemorySize, GEMM_SMEM);
    cudaFuncSetAttribute(k4_fir, cudaFuncAttributeMaxDynamicSharedMemorySize,
                         K4_FLOATS*(int)sizeof(float));

    k0_styles<<<1, 512>>>(w, A, ab);
    k1_wnorm<<<COUT, 256>>>(cw);
    k_pad<<<(BATCH*CIN*XPL + 255)/256, 256>>>(x);
    k_gemm<<<dim3(35, 4, BATCH), 256, GEMM_SMEM>>>(cb);   // launch idx 3
    k4_fir<<<BATCH*COUT, 512, K4_FLOATS*sizeof(float)>>>(out);
}

// round 9
// speedup vs baseline: 3.6100x; 1.3965x over previous
#include <cuda_runtime.h>
#include <cuda_fp16.h>
#include <cstdint>
#include <math.h>

#define BATCH 8
#define CIN   512
#define COUT  512
#define WDIM  512
#define INS   64
#define Y1S   66
#define PLANE 4356
#define UPS   138
#define OUTS  64
#define KTOT  4608
#define XPH   68
#define XPW   72
#define XPL   (XPH*XPW)   // 4896

__device__ float    g_styles[BATCH*CIN];
__device__ float    g_filter[12];
__device__ __half   g_wh[COUT*KTOT];
__device__ float    g_d[BATCH*COUT];
__device__ float    g_y1[BATCH*COUT*PLANE];
__device__ uint32_t g_xhl[BATCH*CIN*XPL];   // per pixel: (lo16<<16)|hi16

// ---------------- PTX helpers (sm_80-baseline only) ----------------
__device__ __forceinline__ uint32_t smem_u32(const void* p) {
    uint32_t a;
    asm("{ .reg .u64 t; cvta.to.shared.u64 t, %1; cvt.u32.u64 %0, t; }" : "=r"(a) : "l"(p));
    return a;
}
#define CP16(dst, src) \
    asm volatile("cp.async.cg.shared.global [%0], [%1], 16;" :: "r"(dst), "l"(src))
#define CPC() asm volatile("cp.async.commit_group;")
#define LDSM4(R, ad) \
    asm volatile("ldmatrix.sync.aligned.m8n8.x4.shared.b16 {%0,%1,%2,%3}, [%4];" \
        : "=r"((R)[0]), "=r"((R)[1]), "=r"((R)[2]), "=r"((R)[3]) : "r"(ad))
#define LDSM4T(R, ad) \
    asm volatile("ldmatrix.sync.aligned.m8n8.x4.trans.shared.b16 {%0,%1,%2,%3}, [%4];" \
        : "=r"((R)[0]), "=r"((R)[1]), "=r"((R)[2]), "=r"((R)[3]) : "r"(ad))
#define MMA(d, a, b0, b1) \
    asm volatile("mma.sync.aligned.m16n8k16.row.col.f32.f16.f16.f32 " \
        "{%0,%1,%2,%3}, {%4,%5,%6,%7}, {%8,%9}, {%0,%1,%2,%3};" \
        : "+f"((d)[0]), "+f"((d)[1]), "+f"((d)[2]), "+f"((d)[3]) \
        : "r"((a)[0]), "r"((a)[1]), "r"((a)[2]), "r"((a)[3]), "r"(b0), "r"(b1))

// atom(32px) -> plane pixel map; atoms 0..136 real. For a%33!=32 and a<136 the
// 32 pixels of an atom are CONTIGUOUS in the plane row (coalesced loads).
__device__ __forceinline__ bool atom_pix(int a, int j, int& P, int& Q) {
    if (a >= 137) return false;
    if (a < 132) {
        int blk = a / 33, ww = a - blk * 33;
        if (ww < 32) { P = blk*16 + (ww>>1); Q = ((ww&1)<<5) + j; return true; }
        P = blk*16 + (j>>1); Q = 64 + (j&1); return true;
    }
    if (a < 136) { int ww = a - 132; P = 64 + (ww>>1); Q = ((ww&1)<<5) + j; return true; }
    P = 64 + (j>>1); Q = 64 + (j&1); return (j < 4);
}
__device__ double bessel_i0(double x) {
    double t = x*x*0.25, term = 1.0, s = 1.0;
    for (int k = 1; k < 64; k++) { term *= t/((double)k*(double)k); s += term; if (term < 1e-18*s) break; }
    return s;
}
__device__ __forceinline__ void split2(float v, __half& h, __half& l) {
    h = __float2half_rn(v);
    l = __float2half_rn(v - __half2float(h));
}

// ============ K0: filter + styles + global style norm ============
__global__ void k0_styles(const float* __restrict__ w, const float* __restrict__ A,
                          const float* __restrict__ bias) {
    int i = threadIdx.x;
    if (i == 0) {
        const double PI = 3.14159265358979323846;
        double a = 2.285*11.0*PI*0.5 + 7.95;
        double beta = (a > 50.0) ? 0.1102*(a-8.7)
                     : (a > 21.0) ? 0.5842*pow(a-21.0,0.4)+0.07886*(a-21.0) : 0.0;
        double i0b = bessel_i0(beta), h[12], sum = 0.0;
        for (int n = 0; n < 12; n++) {
            double m = n - 5.5, sx = 0.5*m;
            double sinc = (sx==0.0) ? 1.0 : sin(PI*sx)/(PI*sx);
            double rt = m/5.5;
            h[n] = 0.5*sinc*bessel_i0(beta*sqrt(fmax(0.0,1.0-rt*rt)))/i0b;
            sum += h[n];
        }
        for (int n = 0; n < 12; n++) g_filter[n] = (float)(h[n]/sum);
    }
    float acc[BATCH];
#pragma unroll
    for (int b = 0; b < BATCH; b++) acc[b] = 0.f;
    const float* Ai = A + (size_t)i*WDIM;
    for (int k = 0; k < WDIM; k++) {
        float av = Ai[k];
#pragma unroll
        for (int b = 0; b < BATCH; b++) acc[b] += w[b*WDIM+k]*av;
    }
    float bi = bias[i], p = 0.f;
#pragma unroll
    for (int b = 0; b < BATCH; b++) { acc[b] = acc[b]*0.04419417382415922f + bi; p += acc[b]*acc[b]; }
    __shared__ float red[512];
    red[i] = p; __syncthreads();
    for (int s = 256; s > 0; s >>= 1) { if (i < s) red[i] += red[i+s]; __syncthreads(); }
    float sc = rsqrtf(red[0]*(1.0f/(BATCH*CIN)));
#pragma unroll
    for (int b = 0; b < BATCH; b++) g_styles[b*CIN+i] = acc[b]*sc;
}

// ============ K1: weight norm + fp16 (hi only) + demod ============
__global__ void k1_wnorm(const float* __restrict__ cw) {
    int o = blockIdx.x, tid = threadIdx.x;
    const float* wo = cw + (size_t)o*(CIN*9);
    __shared__ float red[256];
    float ss = 0.f;
    for (int t = tid; t < CIN*9; t += 256) { float v = wo[t]; ss += v*v; }
    red[tid] = ss; __syncthreads();
    for (int s = 128; s > 0; s >>= 1) { if (tid < s) red[tid] += red[tid+s]; __syncthreads(); }
    float r = rsqrtf(red[0]*(1.0f/(CIN*9)));
    __syncthreads();
    for (int t = tid; t < CIN*9; t += 256) {
        int i = t/9, kk = t - i*9;
        g_wh[(size_t)o*KTOT + kk*512 + i] = __float2half_rn(wo[t]*r);
    }
    float r2 = r*r;
    float part[BATCH];
#pragma unroll
    for (int b = 0; b < BATCH; b++) part[b] = 0.f;
    for (int i = tid; i < CIN; i += 256) {
        float s9 = 0.f;
#pragma unroll
        for (int k = 0; k < 9; k++) { float v = wo[i*9+k]; s9 += v*v; }
        float w2 = s9*r2;
#pragma unroll
        for (int b = 0; b < BATCH; b++) {
            float sv = g_styles[b*CIN+i];
            part[b] += sv*sv*w2;
        }
    }
#pragma unroll
    for (int b = 0; b < BATCH; b++) {
        red[tid] = part[b]; __syncthreads();
        for (int s = 128; s > 0; s >>= 1) { if (tid < s) red[tid] += red[tid+s]; __syncthreads(); }
        if (tid == 0) g_d[b*COUT+o] = rsqrtf(red[0] + 1e-8f);
        __syncthreads();
    }
}

// ============ K_pad: padded style-scaled packed fp16-split input ============
__global__ void k_pad(const float* __restrict__ x) {
    int idx = blockIdx.x*256 + threadIdx.x;
    if (idx >= BATCH*CIN*XPL) return;
    int col = idx % XPW, row = (idx/XPW) % XPH;
    int c = (idx/XPL) % CIN, b = idx/(XPL*CIN);
    int ri = row - 2, ci = col - 2;
    float v = 0.f;
    if (ri >= 0 && ri < INS && ci >= 0 && ci < INS)
        v = x[(((size_t)b*CIN+c)*INS+ri)*INS+ci] * g_styles[b*CIN+c];
    __half h, l; split2(v, h, l);
    g_xhl[idx] = ((uint32_t)__half_as_ushort(l) << 16) | (uint32_t)__half_as_ushort(h);
}

// ============ K_gemm: HMMA (wh)x(xh+xl) implicit conv ============
// SMEM halfs per stage: Ah[128][40]=5120 | Bh[32][136]=4352 | Bl 4352
#define SB_H 5120
#define STGH 13824                     // halfs per stage
#define GEMM_SMEM (2*STGH*2)           // 55296 bytes
#define NCH 144

__global__ __launch_bounds__(256, 2)
void k_gemm(const float* __restrict__ cbias) {
    extern __shared__ __align__(16) char smraw[];
    uint32_t sb = smem_u32(smraw);
    int tid = threadIdx.x, w = tid >> 5, lane = tid & 31;
    int nt = blockIdx.x, oc0 = blockIdx.y * 128, bz = blockIdx.z;
    int wm = w & 1, wn = w >> 1;
    int m0 = wm * 64, n0 = wn * 32;

    // ---- B geometry: warp w loads channels [4w,4w+4) x atoms 0..3 ----
    int pofs[4]; unsigned pv = 0;
#pragma unroll
    for (int t = 0; t < 4; t++) {
        int P, Q;
        if (atom_pix(nt*4 + t, lane, P, Q)) { pofs[t] = P*XPW + Q; pv |= (1u << t); }
        else pofs[t] = 0;
    }

    // ---- A geometry: thread t loads row t>>1, half t&1 (2x CP16) ----
    int arow = tid >> 1, ahalf = tid & 1;

    // ---- ldmatrix base offsets (bytes from stage base) ----
    uint32_t a_base = (uint32_t)(((m0 + (lane & 15))*40 + ((lane >> 4)*8)) * 2);
    uint32_t b_base = (uint32_t)((SB_H + ((lane & 7) + ((lane >> 3) & 1)*8)*136
                                  + n0 + ((lane >> 4)*8)) * 2);

    float acc[64];
#pragma unroll
    for (int t = 0; t < 64; t++) acc[t] = 0.f;

    uint32_t breg[16];

    auto loadA = [&](int ch, int st) {  // cp.async, 16B aligned everywhere
        const __half* src = g_wh + (size_t)(oc0 + arow)*KTOT + ch*32 + ahalf*16;
        uint32_t dst = sb + (uint32_t)((st*STGH + arow*40 + ahalf*16) * 2);
        CP16(dst,      src);
        CP16(dst + 16, src + 8);
    };
    auto ldgB = [&](int ch) {           // coalesced u32 LDG per (channel,atom) row
        int tap = ch >> 4, icb = (ch & 15) << 5;
        int sh = (tap/3)*XPW + (tap - (tap/3)*3);
        const uint32_t* xs = g_xhl + (size_t)bz*(CIN*XPL) + (size_t)(icb + w*4)*XPL + sh;
#pragma unroll
        for (int i = 0; i < 16; i++) {
            int k = i >> 2, a = i & 3;   // channel w*4+k, atom a
            breg[i] = ((pv >> a) & 1u) ? __ldg(xs + (size_t)k*XPL + pofs[a]) : 0u;
        }
    };
    auto stsB = [&](int st) {           // split each pixel u32 -> Bh/Bl halves
        uint32_t base = (uint32_t)((st*STGH + SB_H) * 2);
#pragma unroll
        for (int i = 0; i < 16; i++) {
            int k = (w << 2) + (i >> 2), a = i & 3;
            uint32_t idx = (uint32_t)((k*136 + a*32 + lane) * 2);
            *(unsigned short*)(smraw + base + idx)        = (unsigned short)(breg[i] & 0xFFFF);
            *(unsigned short*)(smraw + base + 8704 + idx) = (unsigned short)(breg[i] >> 16);
        }
    };

    // prologue: fill stage 0
    ldgB(0);
    stsB(0);
    loadA(0, 0); CPC();
    asm volatile("cp.async.wait_group 0;");
    __syncthreads();

    for (int ch = 0; ch < NCH; ch++) {
        int st = ch & 1;
        if (ch + 1 < NCH) {
            ldgB(ch + 1);
            loadA(ch + 1, st ^ 1); CPC();
        }

        uint32_t sbase = sb + (uint32_t)(st * STGH * 2);
#pragma unroll
        for (int k16 = 0; k16 < 2; k16++) {
            uint32_t sA = sbase + a_base + k16*32;
            uint32_t sB = sbase + b_base + k16*(16*136*2);
            uint32_t ah[16], bh[8], bl[8];
#pragma unroll
            for (int mt = 0; mt < 4; mt++) LDSM4(&ah[mt*4], sA + mt*1280);
#pragma unroll
            for (int n2 = 0; n2 < 2; n2++) LDSM4T(&bh[n2*4], sB + n2*32);
#pragma unroll
            for (int mt = 0; mt < 4; mt++)
#pragma unroll
                for (int n = 0; n < 4; n++)
                    MMA(&acc[(mt*4+n)*4], &ah[mt*4],
                        bh[(n>>1)*4 + (n&1)*2], bh[(n>>1)*4 + (n&1)*2 + 1]);
#pragma unroll
            for (int n2 = 0; n2 < 2; n2++) LDSM4T(&bl[n2*4], sB + 8704 + n2*32);
#pragma unroll
            for (int mt = 0; mt < 4; mt++)
#pragma unroll
                for (int n = 0; n < 4; n++)
                    MMA(&acc[(mt*4+n)*4], &ah[mt*4],
                        bl[(n>>1)*4 + (n&1)*2], bl[(n>>1)*4 + (n&1)*2 + 1]);
        }

        if (ch + 1 < NCH) {
            asm volatile("cp.async.wait_group 0;");
            stsB(st ^ 1);
        }
        __syncthreads();
    }

    // ---- epilogue: demod + bias, float2 stores ----
#pragma unroll
    for (int mt = 0; mt < 4; mt++) {
        int ocA = oc0 + m0 + mt*16 + (lane >> 2);
        float dmA = g_d[bz*COUT + ocA],     biA = cbias[ocA];
        float dmB = g_d[bz*COUT + ocA + 8], biB = cbias[ocA + 8];
        size_t rowA = ((size_t)(bz*COUT + ocA)) * PLANE;
        size_t rowB = rowA + (size_t)8 * PLANE;
#pragma unroll
        for (int n = 0; n < 4; n++) {
            int nl = n0 + n*8 + (lane & 3)*2;
            int P, Q;
            if (!atom_pix(nt*4 + (nl >> 5), nl & 31, P, Q)) continue;
            int po = P*Y1S + Q;
            float* c = &acc[(mt*4+n)*4];
            *(float2*)(g_y1 + rowA + po) = make_float2(c[0]*dmA + biA, c[1]*dmA + biA);
            *(float2*)(g_y1 + rowB + po) = make_float2(c[2]*dmB + biB, c[3]*dmB + biB);
        }
    }
}

// ============ K4: fused upFIR -> lrelu/clamp -> downFIR ============
#define SM_VT  0
#define SM_ACT (138*66)
#define K4_FLOATS (138*66 + 138*139)
#define UTAPC(T, FI, LOADEXPR) { int n = rr + (T) - 9; if (n >= 0 && n < 132) { int jph = n >> 1; acc += (LOADEXPR)*fl[FI]; } }

__global__ __launch_bounds__(512)
void k4_fir(float* __restrict__ out) {
    int plane = blockIdx.x, tid = threadIdx.x;
    extern __shared__ float sm[];
    float* vt  = sm + SM_VT;
    float* act = sm + SM_ACT;
    const float* src = g_y1 + (size_t)plane*PLANE;
    float fl[12];
#pragma unroll
    for (int k = 0; k < 12; k++) fl[k] = g_filter[k];

    for (int e = tid; e < UPS*Y1S; e += 512) {
        int rr = e/Y1S, i = e - rr*Y1S;
        float acc = 0.f;
        if ((rr & 1) == 0) {
            UTAPC(1,10, src[jph*Y1S+i]); UTAPC(3,8, src[jph*Y1S+i]); UTAPC(5,6, src[jph*Y1S+i]);
            UTAPC(7,4, src[jph*Y1S+i]); UTAPC(9,2, src[jph*Y1S+i]); UTAPC(11,0, src[jph*Y1S+i]);
        } else {
            UTAPC(0,11, src[jph*Y1S+i]); UTAPC(2,9, src[jph*Y1S+i]); UTAPC(4,7, src[jph*Y1S+i]);
            UTAPC(6,5, src[jph*Y1S+i]); UTAPC(8,3, src[jph*Y1S+i]); UTAPC(10,1, src[jph*Y1S+i]);
        }
        vt[e] = 4.f*acc;
    }
    __syncthreads();
    for (int e = tid; e < UPS*UPS; e += 512) {
        int r = e/UPS, rr = e - r*UPS;
        const float* vr = vt + r*Y1S;
        float acc = 0.f;
        if ((rr & 1) == 0) {
            UTAPC(1,10, vr[jph]); UTAPC(3,8, vr[jph]); UTAPC(5,6, vr[jph]);
            UTAPC(7,4, vr[jph]); UTAPC(9,2, vr[jph]); UTAPC(11,0, vr[jph]);
        } else {
            UTAPC(0,11, vr[jph]); UTAPC(2,9, vr[jph]); UTAPC(4,7, vr[jph]);
            UTAPC(6,5, vr[jph]); UTAPC(8,3, vr[jph]); UTAPC(10,1, vr[jph]);
        }
        float a = (acc >= 0.f ? acc : 0.2f*acc)*1.4142135623730951f;
        act[r*139 + rr] = fminf(fmaxf(a, -256.f), 256.f);
    }
    __syncthreads();
    for (int e = tid; e < OUTS*UPS; e += 512) {
        int rr = e/UPS, j = e - rr*UPS;
        const float* ap = act + (2*rr)*139 + j;
        float acc = 0.f;
#pragma unroll
        for (int t = 0; t < 12; t++) acc += fl[11-t]*ap[t*139];
        vt[rr*UPS + j] = acc;
    }
    __syncthreads();
    float* dst = out + (size_t)plane*(OUTS*OUTS);
    for (int e = tid; e < OUTS*OUTS; e += 512) {
        int rr = e/OUTS, cc = e - rr*OUTS;
        const float* dp = vt + rr*UPS + 2*cc;
        float acc = 0.f;
#pragma unroll
        for (int t = 0; t < 12; t++) acc += fl[11-t]*dp[t];
        dst[rr*OUTS + cc] = acc;
    }
}

// ============ launch ============
extern "C" void kernel_launch(void* const* d_in, const int* in_sizes, int n_in,
                              void* d_out, int out_size) {
    const float* x  = (const float*)d_in[0];
    const float* w  = (const float*)d_in[1];
    const float* A  = (const float*)d_in[2];
    const float* ab = (const float*)d_in[3];
    const float* cw = (const float*)d_in[4];
    const float* cb = (const float*)d_in[5];
    float* out = (float*)d_out;

    cudaFuncSetAttribute(k_gemm, cudaFuncAttributeMaxDynamicSharedMemorySize, GEMM_SMEM);
    cudaFuncSetAttribute(k4_fir, cudaFuncAttributeMaxDynamicSharedMemorySize,
                         K4_FLOATS*(int)sizeof(float));

    k0_styles<<<1, 512>>>(w, A, ab);
    k1_wnorm<<<COUT, 256>>>(cw);
    k_pad<<<(BATCH*CIN*XPL + 255)/256, 256>>>(x);
    k_gemm<<<dim3(35, 4, BATCH), 256, GEMM_SMEM>>>(cb);   // launch idx 3
    k4_fir<<<BATCH*COUT, 512, K4_FLOATS*sizeof(float)>>>(out);
}